// round 16
// baseline (speedup 1.0000x reference)
#include <cuda_runtime.h>
#include <cuda_fp16.h>
#include <cstdint>

#define NN 50000
#define EE 800000
#define ETOT (EE + NN)
#define DD 128
#define NROWS_PAD 50048
#define NBSCAN ((NN + 1023) / 1024)

// ---------------- static device scratch ----------------
__device__ uint32_t g_htf[NROWS_PAD * DD];   // tf32(relu(h)) — produced by attn, consumed by gemm A
__device__ __half g_xlh[NN * DD];            // xl in fp16 (attn gather operand)
__device__ float g_xr[NN * DD];
__device__ int   g_deg[NN];
__device__ int   g_offs[NN + 1];
__device__ int   g_srcs[ETOT];
__device__ int   g_bsums[NBSCAN];
__device__ uint32_t g_WH[4 * 128 * 256];     // pre-converted tf32 weights [layer][k][col 0..255 = Wl|Wr]

__device__ __forceinline__ uint32_t f2tf32(float x) {
    uint32_t r;
    asm volatile("cvt.rna.tf32.f32 %0, %1;" : "=r"(r) : "f"(x));
    return r;
}

// ---------------- CSR build ----------------
__global__ void count_edges(const int* __restrict__ ei) {
    int t = blockIdx.x * blockDim.x + threadIdx.x;
    if (t < ETOT) {
        int dst = (t < EE) ? ei[EE + t] : (t - EE);
        atomicAdd(&g_deg[dst], 1);
    }
}

__global__ void scan_block() {
    __shared__ int sm[256];
    int t = threadIdx.x;
    int base = blockIdx.x * 1024 + t * 4;
    int v0 = (base + 0 < NN) ? g_deg[base + 0] : 0;
    int v1 = (base + 1 < NN) ? g_deg[base + 1] : 0;
    int v2 = (base + 2 < NN) ? g_deg[base + 2] : 0;
    int v3 = (base + 3 < NN) ? g_deg[base + 3] : 0;
    v1 += v0; v2 += v1; v3 += v2;
    sm[t] = v3;
    __syncthreads();
    #pragma unroll
    for (int off = 1; off < 256; off <<= 1) {
        int add = (t >= off) ? sm[t - off] : 0;
        __syncthreads();
        sm[t] += add;
        __syncthreads();
    }
    int prev = (t > 0) ? sm[t - 1] : 0;
    if (base + 0 < NN) g_offs[base + 0] = prev + v0;
    if (base + 1 < NN) g_offs[base + 1] = prev + v1;
    if (base + 2 < NN) g_offs[base + 2] = prev + v2;
    if (base + 3 < NN) g_offs[base + 3] = prev + v3;
    if (t == 255) g_bsums[blockIdx.x] = sm[255];   // block TOTAL
}

// fused spine+fix: 1024-thread blocks, one bsum per block
__global__ void scan_fix() {
    __shared__ int pre;
    int b = blockIdx.x;
    if (threadIdx.x == 0) {
        int acc = 0;
        for (int j = 0; j < b; j++) acc += g_bsums[j];
        pre = acc;
    }
    __syncthreads();
    int i = b * 1024 + threadIdx.x;
    if (i < NN) g_offs[i] = g_offs[i] - g_deg[i] + pre;   // exclusive start
}

// fill bumps g_offs[dst]; afterwards g_offs[d] = end of segment d
__global__ void fill_edges(const int* __restrict__ ei) {
    int t = blockIdx.x * blockDim.x + threadIdx.x;
    if (t < ETOT) {
        int src, dst;
        if (t < EE) { src = ei[t]; dst = ei[EE + t]; }
        else        { src = t - EE; dst = src; }
        int pos = atomicAdd(&g_offs[dst], 1);
        g_srcs[pos] = src;
    }
}

// ---------------- weight pre-convert (tf32) ----------------
__global__ void split_w(const float* __restrict__ Wl, const float* __restrict__ Wr) {
    int i = blockIdx.x * blockDim.x + threadIdx.x;
    if (i >= 4 * 128 * 256) return;
    int layer = i >> 15;
    int rem = i & 32767;
    int k = rem >> 8;
    int c = rem & 255;
    float v = (c < 128) ? Wl[layer * 16384 + k * 128 + c]
                        : Wr[layer * 16384 + k * 128 + (c - 128)];
    g_WH[i] = f2tf32(v);
}

// ---------------- layer 0 GEMM (K=7) ----------------
__global__ void gemm0(const float* __restrict__ x,
                      const float* __restrict__ Wl0, const float* __restrict__ Wr0,
                      const float* __restrict__ bl0, const float* __restrict__ br0) {
    int node = blockIdx.x;
    int j = threadIdx.x;
    __shared__ float xs[7];
    if (j < 7) xs[j] = x[node * 7 + j];
    __syncthreads();
    const float* W = (j < 128) ? Wl0 : Wr0;
    int c = j & 127;
    float acc = (j < 128) ? bl0[c] : br0[c];
    #pragma unroll
    for (int k = 0; k < 7; k++) acc += xs[k] * W[k * 128 + c];
    if (j < 128) g_xlh[node * DD + c] = __float2half_rn(acc);
    else         g_xr[node * DD + c] = acc;
}

// ---------------- TC GEMM (r13: 128x128 per yhalf, occ 2, 3-stage cp.async) ----------------
#define KC 16
#define STAGE_WORDS 4736
#define OFF_BH 2560
#define NSTAGE 3
#define GEMM_SMEM_BYTES (NSTAGE * STAGE_WORDS * 4)

__device__ __forceinline__ void mma_tf32(float c[4], const uint32_t a[4], uint32_t b0, uint32_t b1) {
    asm volatile(
        "mma.sync.aligned.m16n8k8.row.col.f32.tf32.tf32.f32 "
        "{%0,%1,%2,%3}, {%4,%5,%6,%7}, {%8,%9}, {%0,%1,%2,%3};"
        : "+f"(c[0]), "+f"(c[1]), "+f"(c[2]), "+f"(c[3])
        : "r"(a[0]), "r"(a[1]), "r"(a[2]), "r"(a[3]), "r"(b0), "r"(b1));
}

__device__ __forceinline__ void cp16(uint32_t* dst_smem, const uint32_t* src_gmem) {
    uint32_t saddr = (uint32_t)__cvta_generic_to_shared(dst_smem);
    asm volatile("cp.async.cg.shared.global [%0], [%1], 16;" :: "r"(saddr), "l"(src_gmem));
}

__global__ __launch_bounds__(256, 2) void gemm_tc(int layer,
                                                  const float* __restrict__ bl_,
                                                  const float* __restrict__ br_) {
    extern __shared__ uint32_t smem[];

    int tid  = threadIdx.x;
    int lane = tid & 31;
    int wid  = tid >> 5;
    int g    = lane >> 2;
    int tig  = lane & 3;
    int wm   = wid >> 1;
    int wn   = wid & 1;
    int m_base = wm * 32;
    int n_base = wn * 64;
    int row0 = blockIdx.x * 128;
    int yhalf = blockIdx.y;

    const uint32_t* WHbase = g_WH + layer * 32768 + yhalf * 128;

    float c[2][8][4];
    #pragma unroll
    for (int mi = 0; mi < 2; mi++)
        #pragma unroll
        for (int ni = 0; ni < 8; ni++)
            #pragma unroll
            for (int q = 0; q < 4; q++) c[mi][ni][q] = 0.f;

    int ar  = tid >> 1;
    int akq = (tid & 1) * 8;
    int bk  = tid >> 4;
    int bc  = (tid & 15) * 8;
    const uint32_t* a_gp = &g_htf[(size_t)(row0 + ar) * DD + akq];

    #pragma unroll
    for (int st = 0; st < 2; st++) {
        uint32_t* As = smem + st * STAGE_WORDS;
        uint32_t* BH = As + OFF_BH;
        int k0 = st * KC;
        cp16(&As[ar * 20 + akq],     &a_gp[k0]);
        cp16(&As[ar * 20 + akq + 4], &a_gp[k0 + 4]);
        const uint32_t* sH = WHbase + (k0 + bk) * 256 + bc;
        cp16(&BH[bk * 136 + bc],     &sH[0]);
        cp16(&BH[bk * 136 + bc + 4], &sH[4]);
        asm volatile("cp.async.commit_group;");
    }

    int buf = 0;
    for (int it = 0; it < 8; it++) {
        uint32_t* As  = smem + buf * STAGE_WORDS;
        uint32_t* BsH = As + OFF_BH;

        asm volatile("cp.async.wait_group 1;");
        __syncthreads();

        if (it < 6) {
            int k0n = (it + 2) * KC;
            int nbuf = buf + 2; if (nbuf >= NSTAGE) nbuf -= NSTAGE;
            uint32_t* An  = smem + nbuf * STAGE_WORDS;
            uint32_t* BHn = An + OFF_BH;
            cp16(&An[ar * 20 + akq],     &a_gp[k0n]);
            cp16(&An[ar * 20 + akq + 4], &a_gp[k0n + 4]);
            const uint32_t* sH = WHbase + (k0n + bk) * 256 + bc;
            cp16(&BHn[bk * 136 + bc],     &sH[0]);
            cp16(&BHn[bk * 136 + bc + 4], &sH[4]);
            asm volatile("cp.async.commit_group;");
        } else {
            asm volatile("cp.async.commit_group;");
        }

        #pragma unroll
        for (int ks = 0; ks < KC; ks += 8) {
            uint32_t a[2][4];
            #pragma unroll
            for (int mi = 0; mi < 2; mi++) {
                int r = m_base + mi * 16 + g;
                a[mi][0] = As[r * 20 + ks + tig];
                a[mi][1] = As[(r + 8) * 20 + ks + tig];
                a[mi][2] = As[r * 20 + ks + tig + 4];
                a[mi][3] = As[(r + 8) * 20 + ks + tig + 4];
            }
            #pragma unroll
            for (int ni = 0; ni < 8; ni++) {
                int cc = n_base + ni * 8 + g;
                uint32_t b0 = BsH[(ks + tig) * 136 + cc];
                uint32_t b1 = BsH[(ks + tig + 4) * 136 + cc];
                #pragma unroll
                for (int mi = 0; mi < 2; mi++)
                    mma_tf32(c[mi][ni], a[mi], b0, b1);
            }
        }
        buf++; if (buf == NSTAGE) buf = 0;
    }

    // --- epilogue: yhalf=0 -> fp16 xl, yhalf=1 -> fp32 xr ---
    if (yhalf == 0) {
        #pragma unroll
        for (int ni = 0; ni < 8; ni++) {
            int cn = n_base + ni * 8 + tig * 2;
            float b0 = bl_[cn], b1 = bl_[cn + 1];
            #pragma unroll
            for (int mi = 0; mi < 2; mi++) {
                int ra = row0 + m_base + mi * 16 + g;
                int rb = ra + 8;
                if (ra < NN)
                    *(__half2*)&g_xlh[(size_t)ra * DD + cn] =
                        __floats2half2_rn(c[mi][ni][0] + b0, c[mi][ni][1] + b1);
                if (rb < NN)
                    *(__half2*)&g_xlh[(size_t)rb * DD + cn] =
                        __floats2half2_rn(c[mi][ni][2] + b0, c[mi][ni][3] + b1);
            }
        }
    } else {
        #pragma unroll
        for (int ni = 0; ni < 8; ni++) {
            int cn = n_base + ni * 8 + tig * 2;
            float b0 = br_[cn], b1 = br_[cn + 1];
            #pragma unroll
            for (int mi = 0; mi < 2; mi++) {
                int ra = row0 + m_base + mi * 16 + g;
                int rb = ra + 8;
                if (ra < NN)
                    *(float2*)&g_xr[(size_t)ra * DD + cn] =
                        make_float2(c[mi][ni][0] + b0, c[mi][ni][1] + b1);
                if (rb < NN)
                    *(float2*)&g_xr[(size_t)rb * DD + cn] =
                        make_float2(c[mi][ni][2] + b0, c[mi][ni][3] + b1);
            }
        }
    }
}

// ---------------- attention v5: half-warp per edge (16 lanes x 8 dims), abs-leaky, ILP 8 edges ----------------
__global__ __launch_bounds__(256) void attn(const float* __restrict__ avec,
                                            const float* __restrict__ bvec,
                                            float* __restrict__ outp) {
    const unsigned FULL = 0xffffffffu;
    int w = (blockIdx.x * blockDim.x + threadIdx.x) >> 5;
    if (w >= NN) return;
    int lane = threadIdx.x & 31;
    int half = lane >> 4;        // 0/1: edge slot within pair
    int hl   = lane & 15;        // lane-in-half
    int db   = hl * 8;           // 8 dims per lane

    float xr[8];
    *(float4*)&xr[0] = *(const float4*)&g_xr[(size_t)w * DD + db];
    *(float4*)&xr[4] = *(const float4*)&g_xr[(size_t)w * DD + db + 4];
    float a06[8], a04[8];
    {
        float4 aA = *(const float4*)&avec[db];
        float4 aB = *(const float4*)&avec[db + 4];
        float at[8] = {aA.x, aA.y, aA.z, aA.w, aB.x, aB.y, aB.z, aB.w};
        #pragma unroll
        for (int k = 0; k < 8; k++) { a06[k] = 0.6f * at[k]; a04[k] = 0.4f * at[k]; }
    }

    int p   = (w > 0) ? g_offs[w - 1] : 0;   // post-fill: g_offs[d] = end of segment d
    int end = g_offs[w];
    float s = 0.f;
    float acc[8];
    #pragma unroll
    for (int k = 0; k < 8; k++) acc[k] = 0.f;

    // main: 4 pairs = 8 edges per iteration (edge e = p + 2j + half)
    while (p + 8 <= end) {
        uint4 r[4];
        #pragma unroll
        for (int j = 0; j < 4; j++) {
            int src = g_srcs[p + 2 * j + half];
            r[j] = *(const uint4*)&g_xlh[(size_t)src * DD + db];
        }
        float u[4][8], d[4];
        #pragma unroll
        for (int j = 0; j < 4; j++) {
            float2 f0 = __half22float2(*reinterpret_cast<const __half2*>(&r[j].x));
            float2 f1 = __half22float2(*reinterpret_cast<const __half2*>(&r[j].y));
            float2 f2 = __half22float2(*reinterpret_cast<const __half2*>(&r[j].z));
            float2 f3 = __half22float2(*reinterpret_cast<const __half2*>(&r[j].w));
            u[j][0] = f0.x; u[j][1] = f0.y; u[j][2] = f1.x; u[j][3] = f1.y;
            u[j][4] = f2.x; u[j][5] = f2.y; u[j][6] = f3.x; u[j][7] = f3.y;
            float dd = 0.f;
            #pragma unroll
            for (int k = 0; k < 8; k++) {
                float v = u[j][k] + xr[k];
                dd = fmaf(a06[k], v, dd);
                dd = fmaf(a04[k], fabsf(v), dd);
            }
            d[j] = dd;
        }
        #pragma unroll
        for (int off = 1; off <= 8; off <<= 1) {
            #pragma unroll
            for (int j = 0; j < 4; j++) d[j] += __shfl_xor_sync(FULL, d[j], off);
        }
        #pragma unroll
        for (int j = 0; j < 4; j++) {
            float w0 = __expf(d[j]);
            s += w0;
            #pragma unroll
            for (int k = 0; k < 8; k++) acc[k] = fmaf(w0, u[j][k], acc[k]);
        }
        p += 8;
    }

    // tail: one pair (2 edges) per iteration, clamped
    while (p < end) {
        int e  = p + half;
        int pe = (e < end) ? e : (end - 1);
        int src = g_srcs[pe];
        uint4 r = *(const uint4*)&g_xlh[(size_t)src * DD + db];
        float2 f0 = __half22float2(*reinterpret_cast<const __half2*>(&r.x));
        float2 f1 = __half22float2(*reinterpret_cast<const __half2*>(&r.y));
        float2 f2 = __half22float2(*reinterpret_cast<const __half2*>(&r.z));
        float2 f3 = __half22float2(*reinterpret_cast<const __half2*>(&r.w));
        float u[8] = {f0.x, f0.y, f1.x, f1.y, f2.x, f2.y, f3.x, f3.y};
        float dd = 0.f;
        #pragma unroll
        for (int k = 0; k < 8; k++) {
            float v = u[k] + xr[k];
            dd = fmaf(a06[k], v, dd);
            dd = fmaf(a04[k], fabsf(v), dd);
        }
        #pragma unroll
        for (int off = 1; off <= 8; off <<= 1) dd += __shfl_xor_sync(FULL, dd, off);
        if (e >= end) dd = -1e30f;   // invalid half contributes 0
        float w0 = __expf(dd);
        s += w0;
        #pragma unroll
        for (int k = 0; k < 8; k++) acc[k] = fmaf(w0, u[k], acc[k]);
        p += 2;
    }

    // combine the two halves
    s += __shfl_xor_sync(FULL, s, 16);
    #pragma unroll
    for (int k = 0; k < 8; k++) acc[k] += __shfl_xor_sync(FULL, acc[k], 16);

    float inv = 1.f / s;
    float c0 = half ? acc[4] : acc[0];
    float c1 = half ? acc[5] : acc[1];
    float c2 = half ? acc[6] : acc[2];
    float c3 = half ? acc[7] : acc[3];
    int ob = db + half * 4;
    float4 b4 = *(const float4*)&bvec[ob];
    float o0 = c0 * inv + b4.x;
    float o1 = c1 * inv + b4.y;
    float o2 = c2 * inv + b4.z;
    float o3 = c3 * inv + b4.w;
    if (outp) {
        *(float4*)&outp[(size_t)w * DD + ob] = make_float4(o0, o1, o2, o3);
    } else {
        uint4 t;
        t.x = f2tf32(fmaxf(o0, 0.f));
        t.y = f2tf32(fmaxf(o1, 0.f));
        t.z = f2tf32(fmaxf(o2, 0.f));
        t.w = f2tf32(fmaxf(o3, 0.f));
        *(uint4*)&g_htf[(size_t)w * DD + ob] = t;
    }
}

// ---------------- launch ----------------
extern "C" void kernel_launch(void* const* d_in, const int* in_sizes, int n_in,
                              void* d_out, int out_size) {
    const float* x    = (const float*)d_in[0];
    const int*   ei   = (const int*)d_in[1];
    const float* Wl0  = (const float*)d_in[2];
    const float* Wr0  = (const float*)d_in[3];
    const float* bl0  = (const float*)d_in[4];
    const float* br0  = (const float*)d_in[5];
    const float* Wl   = (const float*)d_in[6];
    const float* Wr   = (const float*)d_in[7];
    const float* bl   = (const float*)d_in[8];
    const float* br   = (const float*)d_in[9];
    const float* att  = (const float*)d_in[10];
    const float* bias = (const float*)d_in[11];
    float* out = (float*)d_out;

    cudaFuncSetAttribute(gemm_tc, cudaFuncAttributeMaxDynamicSharedMemorySize, GEMM_SMEM_BYTES);

    void* deg_ptr = nullptr;
    cudaGetSymbolAddress(&deg_ptr, g_deg);
    cudaMemsetAsync(deg_ptr, 0, NN * sizeof(int));       // memset node, not a kernel

    count_edges<<<(ETOT + 255) / 256, 256>>>(ei);
    scan_block<<<NBSCAN, 256>>>();
    scan_fix<<<NBSCAN, 1024>>>();
    fill_edges<<<(ETOT + 255) / 256, 256>>>(ei);
    split_w<<<(4 * 128 * 256 + 255) / 256, 256>>>(Wl, Wr);

    const int attn_blocks = (NN * 32 + 255) / 256;
    dim3 tc_grid((NN + 127) / 128, 2);

    gemm0<<<NN, 256>>>(x, Wl0, Wr0, bl0, br0);
    attn<<<attn_blocks, 256>>>(att, bias, nullptr);

    for (int t = 1; t < 5; t++) {
        gemm_tc<<<tc_grid, 256, GEMM_SMEM_BYTES>>>(t - 1, bl + (size_t)(t - 1) * 128,
                                                   br + (size_t)(t - 1) * 128);
        attn<<<attn_blocks, 256>>>(att + (size_t)t * 128, bias + (size_t)t * 128,
                                   (t == 4) ? out : nullptr);
    }
}

// round 17
// speedup vs baseline: 1.0653x; 1.0653x over previous
#include <cuda_runtime.h>
#include <cuda_fp16.h>
#include <cstdint>

#define NN 50000
#define EE 800000
#define ETOT (EE + NN)
#define DD 128
#define NROWS_PAD 50048
#define NBSCAN ((NN + 1023) / 1024)

// ---------------- static device scratch ----------------
__device__ uint32_t g_htf[NROWS_PAD * DD];   // tf32(relu(h)) — produced by attn, consumed by gemm A
__device__ __half g_xlh[NN * DD];            // xl in fp16 (attn gather operand)
__device__ float g_xr[NN * DD];
__device__ int   g_deg[NN];
__device__ int   g_offs[NN + 1];
__device__ int   g_srcs[ETOT];
__device__ int   g_bsums[NBSCAN];
__device__ uint32_t g_WH[4 * 128 * 256];     // pre-converted tf32 weights [layer][k][col 0..255 = Wl|Wr]

__device__ __forceinline__ uint32_t f2tf32(float x) {
    uint32_t r;
    asm volatile("cvt.rna.tf32.f32 %0, %1;" : "=r"(r) : "f"(x));
    return r;
}

// ---------------- CSR build ----------------
__global__ void count_edges(const int* __restrict__ ei) {
    int t = blockIdx.x * blockDim.x + threadIdx.x;
    if (t < ETOT) {
        int dst = (t < EE) ? ei[EE + t] : (t - EE);
        atomicAdd(&g_deg[dst], 1);
    }
}

__global__ void scan_block() {
    __shared__ int sm[256];
    int t = threadIdx.x;
    int base = blockIdx.x * 1024 + t * 4;
    int v0 = (base + 0 < NN) ? g_deg[base + 0] : 0;
    int v1 = (base + 1 < NN) ? g_deg[base + 1] : 0;
    int v2 = (base + 2 < NN) ? g_deg[base + 2] : 0;
    int v3 = (base + 3 < NN) ? g_deg[base + 3] : 0;
    v1 += v0; v2 += v1; v3 += v2;
    sm[t] = v3;
    __syncthreads();
    #pragma unroll
    for (int off = 1; off < 256; off <<= 1) {
        int add = (t >= off) ? sm[t - off] : 0;
        __syncthreads();
        sm[t] += add;
        __syncthreads();
    }
    int prev = (t > 0) ? sm[t - 1] : 0;
    if (base + 0 < NN) g_offs[base + 0] = prev + v0;
    if (base + 1 < NN) g_offs[base + 1] = prev + v1;
    if (base + 2 < NN) g_offs[base + 2] = prev + v2;
    if (base + 3 < NN) g_offs[base + 3] = prev + v3;
    if (t == 255) g_bsums[blockIdx.x] = sm[255];   // block TOTAL
}

// fused spine+fix: 1024-thread blocks, one bsum prefix per block
__global__ void scan_fix() {
    __shared__ int pre;
    int b = blockIdx.x;
    if (threadIdx.x == 0) {
        int acc = 0;
        for (int j = 0; j < b; j++) acc += g_bsums[j];
        pre = acc;
    }
    __syncthreads();
    int i = b * 1024 + threadIdx.x;
    if (i < NN) g_offs[i] = g_offs[i] - g_deg[i] + pre;   // exclusive start
}

// fill bumps g_offs[dst]; afterwards g_offs[d] = end of segment d
__global__ void fill_edges(const int* __restrict__ ei) {
    int t = blockIdx.x * blockDim.x + threadIdx.x;
    if (t < ETOT) {
        int src, dst;
        if (t < EE) { src = ei[t]; dst = ei[EE + t]; }
        else        { src = t - EE; dst = src; }
        int pos = atomicAdd(&g_offs[dst], 1);
        g_srcs[pos] = src;
    }
}

// ---------------- weight pre-convert (tf32) ----------------
__global__ void split_w(const float* __restrict__ Wl, const float* __restrict__ Wr) {
    int i = blockIdx.x * blockDim.x + threadIdx.x;
    if (i >= 4 * 128 * 256) return;
    int layer = i >> 15;
    int rem = i & 32767;
    int k = rem >> 8;
    int c = rem & 255;
    float v = (c < 128) ? Wl[layer * 16384 + k * 128 + c]
                        : Wr[layer * 16384 + k * 128 + (c - 128)];
    g_WH[i] = f2tf32(v);
}

// ---------------- layer 0 GEMM (K=7) ----------------
__global__ void gemm0(const float* __restrict__ x,
                      const float* __restrict__ Wl0, const float* __restrict__ Wr0,
                      const float* __restrict__ bl0, const float* __restrict__ br0) {
    int node = blockIdx.x;
    int j = threadIdx.x;
    __shared__ float xs[7];
    if (j < 7) xs[j] = x[node * 7 + j];
    __syncthreads();
    const float* W = (j < 128) ? Wl0 : Wr0;
    int c = j & 127;
    float acc = (j < 128) ? bl0[c] : br0[c];
    #pragma unroll
    for (int k = 0; k < 7; k++) acc += xs[k] * W[k * 128 + c];
    if (j < 128) g_xlh[node * DD + c] = __float2half_rn(acc);
    else         g_xr[node * DD + c] = acc;
}

// ---------------- TC GEMM (r13: 128x128 per yhalf, occ 2, 3-stage cp.async) ----------------
#define KC 16
#define STAGE_WORDS 4736
#define OFF_BH 2560
#define NSTAGE 3
#define GEMM_SMEM_BYTES (NSTAGE * STAGE_WORDS * 4)

__device__ __forceinline__ void mma_tf32(float c[4], const uint32_t a[4], uint32_t b0, uint32_t b1) {
    asm volatile(
        "mma.sync.aligned.m16n8k8.row.col.f32.tf32.tf32.f32 "
        "{%0,%1,%2,%3}, {%4,%5,%6,%7}, {%8,%9}, {%0,%1,%2,%3};"
        : "+f"(c[0]), "+f"(c[1]), "+f"(c[2]), "+f"(c[3])
        : "r"(a[0]), "r"(a[1]), "r"(a[2]), "r"(a[3]), "r"(b0), "r"(b1));
}

__device__ __forceinline__ void cp16(uint32_t* dst_smem, const uint32_t* src_gmem) {
    uint32_t saddr = (uint32_t)__cvta_generic_to_shared(dst_smem);
    asm volatile("cp.async.cg.shared.global [%0], [%1], 16;" :: "r"(saddr), "l"(src_gmem));
}

__global__ __launch_bounds__(256, 2) void gemm_tc(int layer,
                                                  const float* __restrict__ bl_,
                                                  const float* __restrict__ br_) {
    extern __shared__ uint32_t smem[];

    int tid  = threadIdx.x;
    int lane = tid & 31;
    int wid  = tid >> 5;
    int g    = lane >> 2;
    int tig  = lane & 3;
    int wm   = wid >> 1;
    int wn   = wid & 1;
    int m_base = wm * 32;
    int n_base = wn * 64;
    int row0 = blockIdx.x * 128;
    int yhalf = blockIdx.y;

    const uint32_t* WHbase = g_WH + layer * 32768 + yhalf * 128;

    float c[2][8][4];
    #pragma unroll
    for (int mi = 0; mi < 2; mi++)
        #pragma unroll
        for (int ni = 0; ni < 8; ni++)
            #pragma unroll
            for (int q = 0; q < 4; q++) c[mi][ni][q] = 0.f;

    int ar  = tid >> 1;
    int akq = (tid & 1) * 8;
    int bk  = tid >> 4;
    int bc  = (tid & 15) * 8;
    const uint32_t* a_gp = &g_htf[(size_t)(row0 + ar) * DD + akq];

    #pragma unroll
    for (int st = 0; st < 2; st++) {
        uint32_t* As = smem + st * STAGE_WORDS;
        uint32_t* BH = As + OFF_BH;
        int k0 = st * KC;
        cp16(&As[ar * 20 + akq],     &a_gp[k0]);
        cp16(&As[ar * 20 + akq + 4], &a_gp[k0 + 4]);
        const uint32_t* sH = WHbase + (k0 + bk) * 256 + bc;
        cp16(&BH[bk * 136 + bc],     &sH[0]);
        cp16(&BH[bk * 136 + bc + 4], &sH[4]);
        asm volatile("cp.async.commit_group;");
    }

    int buf = 0;
    for (int it = 0; it < 8; it++) {
        uint32_t* As  = smem + buf * STAGE_WORDS;
        uint32_t* BsH = As + OFF_BH;

        asm volatile("cp.async.wait_group 1;");
        __syncthreads();

        if (it < 6) {
            int k0n = (it + 2) * KC;
            int nbuf = buf + 2; if (nbuf >= NSTAGE) nbuf -= NSTAGE;
            uint32_t* An  = smem + nbuf * STAGE_WORDS;
            uint32_t* BHn = An + OFF_BH;
            cp16(&An[ar * 20 + akq],     &a_gp[k0n]);
            cp16(&An[ar * 20 + akq + 4], &a_gp[k0n + 4]);
            const uint32_t* sH = WHbase + (k0n + bk) * 256 + bc;
            cp16(&BHn[bk * 136 + bc],     &sH[0]);
            cp16(&BHn[bk * 136 + bc + 4], &sH[4]);
            asm volatile("cp.async.commit_group;");
        } else {
            asm volatile("cp.async.commit_group;");
        }

        #pragma unroll
        for (int ks = 0; ks < KC; ks += 8) {
            uint32_t a[2][4];
            #pragma unroll
            for (int mi = 0; mi < 2; mi++) {
                int r = m_base + mi * 16 + g;
                a[mi][0] = As[r * 20 + ks + tig];
                a[mi][1] = As[(r + 8) * 20 + ks + tig];
                a[mi][2] = As[r * 20 + ks + tig + 4];
                a[mi][3] = As[(r + 8) * 20 + ks + tig + 4];
            }
            #pragma unroll
            for (int ni = 0; ni < 8; ni++) {
                int cc = n_base + ni * 8 + g;
                uint32_t b0 = BsH[(ks + tig) * 136 + cc];
                uint32_t b1 = BsH[(ks + tig + 4) * 136 + cc];
                #pragma unroll
                for (int mi = 0; mi < 2; mi++)
                    mma_tf32(c[mi][ni], a[mi], b0, b1);
            }
        }
        buf++; if (buf == NSTAGE) buf = 0;
    }

    // --- epilogue: yhalf=0 -> fp16 xl, yhalf=1 -> fp32 xr ---
    if (yhalf == 0) {
        #pragma unroll
        for (int ni = 0; ni < 8; ni++) {
            int cn = n_base + ni * 8 + tig * 2;
            float b0 = bl_[cn], b1 = bl_[cn + 1];
            #pragma unroll
            for (int mi = 0; mi < 2; mi++) {
                int ra = row0 + m_base + mi * 16 + g;
                int rb = ra + 8;
                if (ra < NN)
                    *(__half2*)&g_xlh[(size_t)ra * DD + cn] =
                        __floats2half2_rn(c[mi][ni][0] + b0, c[mi][ni][1] + b1);
                if (rb < NN)
                    *(__half2*)&g_xlh[(size_t)rb * DD + cn] =
                        __floats2half2_rn(c[mi][ni][2] + b0, c[mi][ni][3] + b1);
            }
        }
    } else {
        #pragma unroll
        for (int ni = 0; ni < 8; ni++) {
            int cn = n_base + ni * 8 + tig * 2;
            float b0 = br_[cn], b1 = br_[cn + 1];
            #pragma unroll
            for (int mi = 0; mi < 2; mi++) {
                int ra = row0 + m_base + mi * 16 + g;
                int rb = ra + 8;
                if (ra < NN)
                    *(float2*)&g_xr[(size_t)ra * DD + cn] =
                        make_float2(c[mi][ni][0] + b0, c[mi][ni][1] + b1);
                if (rb < NN)
                    *(float2*)&g_xr[(size_t)rb * DD + cn] =
                        make_float2(c[mi][ni][2] + b0, c[mi][ni][3] + b1);
            }
        }
    }
}

// ---------------- attention (r15 proven): warp per node, no-max softmax, ILP-4 + prefetch, fp16 gather ----------------
__device__ __forceinline__ float4 h4_to_f4(uint2 r) {
    float2 f0 = __half22float2(*reinterpret_cast<const __half2*>(&r.x));
    float2 f1 = __half22float2(*reinterpret_cast<const __half2*>(&r.y));
    return make_float4(f0.x, f0.y, f1.x, f1.y);
}

__device__ __forceinline__ float dleaky(float4 c, float4 xr, float4 a, float d) {
    float v;
    v = c.x + xr.x; v = (v > 0.f) ? v : 0.2f * v; d = fmaf(v, a.x, d);
    v = c.y + xr.y; v = (v > 0.f) ? v : 0.2f * v; d = fmaf(v, a.y, d);
    v = c.z + xr.z; v = (v > 0.f) ? v : 0.2f * v; d = fmaf(v, a.z, d);
    v = c.w + xr.w; v = (v > 0.f) ? v : 0.2f * v; d = fmaf(v, a.w, d);
    return d;
}

__global__ void attn(const float* __restrict__ avec, const float* __restrict__ bvec,
                     float* __restrict__ outp) {
    const unsigned FULL = 0xffffffffu;
    int w = (blockIdx.x * blockDim.x + threadIdx.x) >> 5;
    if (w >= NN) return;
    int lane = threadIdx.x & 31;

    float4 xr4 = *(float4*)&g_xr[(size_t)w * DD + lane * 4];
    float4 a4  = *(const float4*)&avec[lane * 4];

    int p   = (w > 0) ? g_offs[w - 1] : 0;
    int end = g_offs[w];
    float s = 0.f;
    float ax = 0.f, ay = 0.f, az = 0.f, aw = 0.f;

    int p4end = p + ((end - p) & ~3);

    uint2 r0, r1, r2, r3;
    if (p < p4end) {
        int s0 = g_srcs[p], s1 = g_srcs[p + 1], s2 = g_srcs[p + 2], s3 = g_srcs[p + 3];
        r0 = *(const uint2*)&g_xlh[(size_t)s0 * DD + lane * 4];
        r1 = *(const uint2*)&g_xlh[(size_t)s1 * DD + lane * 4];
        r2 = *(const uint2*)&g_xlh[(size_t)s2 * DD + lane * 4];
        r3 = *(const uint2*)&g_xlh[(size_t)s3 * DD + lane * 4];
    }

    while (p < p4end) {
        float4 u0 = h4_to_f4(r0), u1 = h4_to_f4(r1), u2 = h4_to_f4(r2), u3 = h4_to_f4(r3);
        int pn = p + 4;
        if (pn < p4end) {
            int s0 = g_srcs[pn], s1 = g_srcs[pn + 1], s2 = g_srcs[pn + 2], s3 = g_srcs[pn + 3];
            r0 = *(const uint2*)&g_xlh[(size_t)s0 * DD + lane * 4];
            r1 = *(const uint2*)&g_xlh[(size_t)s1 * DD + lane * 4];
            r2 = *(const uint2*)&g_xlh[(size_t)s2 * DD + lane * 4];
            r3 = *(const uint2*)&g_xlh[(size_t)s3 * DD + lane * 4];
        }

        float d0 = dleaky(u0, xr4, a4, 0.f);
        float d1 = dleaky(u1, xr4, a4, 0.f);
        float d2 = dleaky(u2, xr4, a4, 0.f);
        float d3 = dleaky(u3, xr4, a4, 0.f);

        #pragma unroll
        for (int off = 16; off >= 1; off >>= 1) {
            d0 += __shfl_xor_sync(FULL, d0, off);
            d1 += __shfl_xor_sync(FULL, d1, off);
            d2 += __shfl_xor_sync(FULL, d2, off);
            d3 += __shfl_xor_sync(FULL, d3, off);
        }

        float w0 = __expf(d0), w1 = __expf(d1), w2 = __expf(d2), w3 = __expf(d3);
        s += (w0 + w1) + (w2 + w3);
        ax += w0 * u0.x + w1 * u1.x + w2 * u2.x + w3 * u3.x;
        ay += w0 * u0.y + w1 * u1.y + w2 * u2.y + w3 * u3.y;
        az += w0 * u0.z + w1 * u1.z + w2 * u2.z + w3 * u3.z;
        aw += w0 * u0.w + w1 * u1.w + w2 * u2.w + w3 * u3.w;
        p = pn;
    }

    while (p < end) {
        int s0 = g_srcs[p];
        float4 u0 = h4_to_f4(*(const uint2*)&g_xlh[(size_t)s0 * DD + lane * 4]);
        float d0 = dleaky(u0, xr4, a4, 0.f);
        #pragma unroll
        for (int off = 16; off >= 1; off >>= 1)
            d0 += __shfl_xor_sync(FULL, d0, off);
        float w0 = __expf(d0);
        s += w0;
        ax += w0 * u0.x;
        ay += w0 * u0.y;
        az += w0 * u0.z;
        aw += w0 * u0.w;
        p++;
    }

    float inv = 1.f / s;
    float4 b4 = *(const float4*)&bvec[lane * 4];
    float4 r = make_float4(ax * inv + b4.x, ay * inv + b4.y,
                           az * inv + b4.z, aw * inv + b4.w);
    if (outp) {
        *(float4*)&outp[(size_t)w * DD + lane * 4] = r;
    } else {
        uint4 t;
        t.x = f2tf32(fmaxf(r.x, 0.f));
        t.y = f2tf32(fmaxf(r.y, 0.f));
        t.z = f2tf32(fmaxf(r.z, 0.f));
        t.w = f2tf32(fmaxf(r.w, 0.f));
        *(uint4*)&g_htf[(size_t)w * DD + lane * 4] = t;
    }
}

// ---------------- launch ----------------
extern "C" void kernel_launch(void* const* d_in, const int* in_sizes, int n_in,
                              void* d_out, int out_size) {
    const float* x    = (const float*)d_in[0];
    const int*   ei   = (const int*)d_in[1];
    const float* Wl0  = (const float*)d_in[2];
    const float* Wr0  = (const float*)d_in[3];
    const float* bl0  = (const float*)d_in[4];
    const float* br0  = (const float*)d_in[5];
    const float* Wl   = (const float*)d_in[6];
    const float* Wr   = (const float*)d_in[7];
    const float* bl   = (const float*)d_in[8];
    const float* br   = (const float*)d_in[9];
    const float* att  = (const float*)d_in[10];
    const float* bias = (const float*)d_in[11];
    float* out = (float*)d_out;

    cudaFuncSetAttribute(gemm_tc, cudaFuncAttributeMaxDynamicSharedMemorySize, GEMM_SMEM_BYTES);

    void* deg_ptr = nullptr;
    cudaGetSymbolAddress(&deg_ptr, g_deg);
    cudaMemsetAsync(deg_ptr, 0, NN * sizeof(int));

    count_edges<<<(ETOT + 255) / 256, 256>>>(ei);
    scan_block<<<NBSCAN, 256>>>();
    scan_fix<<<NBSCAN, 1024>>>();
    fill_edges<<<(ETOT + 255) / 256, 256>>>(ei);
    split_w<<<(4 * 128 * 256 + 255) / 256, 256>>>(Wl, Wr);

    const int attn_blocks = (NN * 32 + 255) / 256;
    dim3 tc_grid((NN + 127) / 128, 2);

    gemm0<<<NN, 256>>>(x, Wl0, Wr0, bl0, br0);
    attn<<<attn_blocks, 256>>>(att, bias, nullptr);

    for (int t = 1; t < 5; t++) {
        gemm_tc<<<tc_grid, 256, GEMM_SMEM_BYTES>>>(t - 1, bl + (size_t)(t - 1) * 128,
                                                   br + (size_t)(t - 1) * 128);
        attn<<<attn_blocks, 256>>>(att + (size_t)t * 128, bias + (size_t)t * 128,
                                   (t == 4) ? out : nullptr);
    }
}